// round 3
// baseline (speedup 1.0000x reference)
#include <cuda_runtime.h>
#include <cuda_bf16.h>
#include <cstdint>

#define BDIM 16384
#define CDIM 1024
#define DDIM 128

__device__ float s_theta[BDIM * DDIM];
__device__ float s_phi[BDIM * DDIM];
__device__ float s_g[BDIM * DDIM];
__device__ float s_y[BDIM * DDIM];

__device__ __nv_bfloat16 s_gwh[DDIM * CDIM];
__device__ __nv_bfloat16 s_gwl[DDIM * CDIM];
__device__ __nv_bfloat16 s_thwh[DDIM * CDIM];
__device__ __nv_bfloat16 s_thwl[DDIM * CDIM];
__device__ __nv_bfloat16 s_phwh[DDIM * CDIM];
__device__ __nv_bfloat16 s_phwl[DDIM * CDIM];
__device__ __nv_bfloat16 s_Wwh[CDIM * DDIM];
__device__ __nv_bfloat16 s_Wwl[CDIM * DDIM];

__device__ __forceinline__ unsigned pkb(__nv_bfloat16 a, __nv_bfloat16 b) {
    return (unsigned)__bfloat16_as_ushort(a) | ((unsigned)__bfloat16_as_ushort(b) << 16);
}
__device__ __forceinline__ void ldsm4(uint32_t* r, uint32_t addr) {
    asm volatile("ldmatrix.sync.aligned.m8n8.x4.shared.b16 {%0,%1,%2,%3}, [%4];"
                 : "=r"(r[0]), "=r"(r[1]), "=r"(r[2]), "=r"(r[3]) : "r"(addr));
}
__device__ __forceinline__ void mma16816(float* c, const uint32_t* a, uint32_t b0, uint32_t b1) {
    asm volatile(
        "mma.sync.aligned.m16n8k16.row.col.f32.bf16.bf16.f32 "
        "{%0,%1,%2,%3}, {%4,%5,%6,%7}, {%8,%9}, {%0,%1,%2,%3};"
        : "+f"(c[0]), "+f"(c[1]), "+f"(c[2]), "+f"(c[3])
        : "r"(a[0]), "r"(a[1]), "r"(a[2]), "r"(a[3]), "r"(b0), "r"(b1));
}
__device__ __forceinline__ void cp16(uint32_t dst, const void* src) {
    asm volatile("cp.async.cg.shared.global [%0], [%1], 16;" :: "r"(dst), "l"(src));
}
#define CP_COMMIT() asm volatile("cp.async.commit_group;")
#define CP_WAIT1()  asm volatile("cp.async.wait_group 1;")

__device__ __forceinline__ float ex2f(float x) {
    float r; asm("ex2.approx.ftz.f32 %0, %1;" : "=f"(r) : "f"(x)); return r;
}

// ---------- weight hi/lo split ----------
__global__ void split_kernel(const float* __restrict__ in,
                             __nv_bfloat16* __restrict__ hi,
                             __nv_bfloat16* __restrict__ lo, int n4) {
    int i = blockIdx.x * blockDim.x + threadIdx.x;
    int stride = gridDim.x * blockDim.x;
    const float4* in4 = reinterpret_cast<const float4*>(in);
    uint2* h2 = reinterpret_cast<uint2*>(hi);
    uint2* l2 = reinterpret_cast<uint2*>(lo);
    for (; i < n4; i += stride) {
        float4 v = in4[i];
        __nv_bfloat16 a = __float2bfloat16(v.x), b = __float2bfloat16(v.y);
        __nv_bfloat16 c = __float2bfloat16(v.z), d = __float2bfloat16(v.w);
        __nv_bfloat16 e = __float2bfloat16(v.x - __bfloat162float(a));
        __nv_bfloat16 f = __float2bfloat16(v.y - __bfloat162float(b));
        __nv_bfloat16 g = __float2bfloat16(v.z - __bfloat162float(c));
        __nv_bfloat16 h = __float2bfloat16(v.w - __bfloat162float(d));
        h2[i] = make_uint2(pkb(a, b), pkb(c, d));
        l2[i] = make_uint2(pkb(e, f), pkb(g, h));
    }
}

// ---------- split GEMM: out[M,N]=A[M,K]@W[N,K]^T + bias (+resid) ----------
// CTA 128x128, BK=32, 8 warps (4m x 2n), warp tile 32x64.
#define SAP 40
#define GEMM_SMEM 61440

__global__ void __launch_bounds__(256)
gemm_split_kernel(const float* __restrict__ A,
                  const __nv_bfloat16* __restrict__ Wh,
                  const __nv_bfloat16* __restrict__ Wl,
                  const float* __restrict__ bias,
                  const float* __restrict__ resid,
                  float* __restrict__ out, int K, int ldo) {
    extern __shared__ unsigned char smem[];
    const int tid = threadIdx.x, lane = tid & 31, wid = tid >> 5;
    const int wm = (wid & 3) * 32, wn = (wid >> 2) * 64;
    const int bm = blockIdx.x * 128, n0 = blockIdx.y * 128;
    const __nv_bfloat16* Whp = Wh + (size_t)n0 * K;
    const __nv_bfloat16* Wlp = Wl + (size_t)n0 * K;
    const uint32_t sbase = (uint32_t)__cvta_generic_to_shared(smem);
    const uint32_t oAl = 10240, oW = 20480;

    float acc[2][8][4];
#pragma unroll
    for (int a = 0; a < 2; a++)
#pragma unroll
        for (int b = 0; b < 8; b++)
#pragma unroll
            for (int c = 0; c < 4; c++) acc[a][b][c] = 0.f;

    const int NC = K / 32;
    float4 stage[4];
    {
#pragma unroll
        for (int i = 0; i < 4; i++) {
            int q = tid + 256 * i;
            stage[i] = *reinterpret_cast<const float4*>(
                &A[(size_t)(bm + (q >> 3)) * K + (q & 7) * 4]);
        }
#pragma unroll
        for (int i = 0; i < 2; i++) {
            int q = tid + 256 * i;
            int r = q >> 2, cc = q & 3;
            uint32_t d = sbase + oW + (uint32_t)(r * SAP + cc * 8) * 2;
            cp16(d, Whp + (size_t)r * K + cc * 8);
            cp16(d + 10240, Wlp + (size_t)r * K + cc * 8);
        }
        CP_COMMIT();
    }

    for (int c = 0; c < NC; c++) {
#pragma unroll
        for (int i = 0; i < 4; i++) {
            int q = tid + 256 * i;
            int r = q >> 3, c4 = q & 7;
            float4 v = stage[i];
            __nv_bfloat16 a0 = __float2bfloat16(v.x), a1 = __float2bfloat16(v.y);
            __nv_bfloat16 a2 = __float2bfloat16(v.z), a3 = __float2bfloat16(v.w);
            __nv_bfloat16 l0 = __float2bfloat16(v.x - __bfloat162float(a0));
            __nv_bfloat16 l1 = __float2bfloat16(v.y - __bfloat162float(a1));
            __nv_bfloat16 l2 = __float2bfloat16(v.z - __bfloat162float(a2));
            __nv_bfloat16 l3 = __float2bfloat16(v.w - __bfloat162float(a3));
            size_t eoff = (size_t)(r * SAP + c4 * 4) * 2;
            *reinterpret_cast<uint2*>(smem + eoff) = make_uint2(pkb(a0, a1), pkb(a2, a3));
            *reinterpret_cast<uint2*>(smem + oAl + eoff) = make_uint2(pkb(l0, l1), pkb(l2, l3));
        }
        if (c + 1 < NC) {
            int kk = (c + 1) * 32, buf = (c + 1) & 1;
#pragma unroll
            for (int i = 0; i < 4; i++) {
                int q = tid + 256 * i;
                stage[i] = *reinterpret_cast<const float4*>(
                    &A[(size_t)(bm + (q >> 3)) * K + kk + (q & 7) * 4]);
            }
#pragma unroll
            for (int i = 0; i < 2; i++) {
                int q = tid + 256 * i;
                int r = q >> 2, cc = q & 3;
                uint32_t d = sbase + oW + (uint32_t)buf * 20480 +
                             (uint32_t)(r * SAP + cc * 8) * 2;
                cp16(d, Whp + (size_t)r * K + kk + cc * 8);
                cp16(d + 10240, Wlp + (size_t)r * K + kk + cc * 8);
            }
        }
        CP_COMMIT();
        CP_WAIT1();
        __syncthreads();

        const uint32_t wb = sbase + oW + (uint32_t)(c & 1) * 20480;
#pragma unroll
        for (int ks = 0; ks < 2; ks++) {
            uint32_t ah[2][4], al[2][4], wf[4][4];
#pragma unroll
            for (int mt = 0; mt < 2; mt++) {
                uint32_t aoff = (uint32_t)((wm + mt * 16 + (lane & 15)) * SAP +
                                           ks * 16 + (lane >> 4) * 8) * 2;
                ldsm4(ah[mt], sbase + aoff);
                ldsm4(al[mt], sbase + oAl + aoff);
            }
#pragma unroll
            for (int p = 0; p < 4; p++) {
                uint32_t woff = (uint32_t)((wn + p * 16 + (lane & 7) + ((lane >> 4) & 1) * 8) * SAP +
                                           ks * 16 + ((lane >> 3) & 1) * 8) * 2;
                ldsm4(wf[p], wb + woff);
            }
#pragma unroll
            for (int mt = 0; mt < 2; mt++)
#pragma unroll
                for (int p = 0; p < 4; p++) {
                    mma16816(acc[mt][2 * p], ah[mt], wf[p][0], wf[p][1]);
                    mma16816(acc[mt][2 * p + 1], ah[mt], wf[p][2], wf[p][3]);
                    mma16816(acc[mt][2 * p], al[mt], wf[p][0], wf[p][1]);
                    mma16816(acc[mt][2 * p + 1], al[mt], wf[p][2], wf[p][3]);
                }
#pragma unroll
            for (int p = 0; p < 4; p++) {
                uint32_t woff = (uint32_t)((wn + p * 16 + (lane & 7) + ((lane >> 4) & 1) * 8) * SAP +
                                           ks * 16 + ((lane >> 3) & 1) * 8) * 2;
                ldsm4(wf[p], wb + 10240 + woff);
            }
#pragma unroll
            for (int mt = 0; mt < 2; mt++)
#pragma unroll
                for (int p = 0; p < 4; p++) {
                    mma16816(acc[mt][2 * p], ah[mt], wf[p][0], wf[p][1]);
                    mma16816(acc[mt][2 * p + 1], ah[mt], wf[p][2], wf[p][3]);
                }
        }
        __syncthreads();
    }

#pragma unroll
    for (int mt = 0; mt < 2; mt++) {
        int r0 = bm + wm + mt * 16 + (lane >> 2);
#pragma unroll
        for (int nt = 0; nt < 8; nt++) {
            int ccol = n0 + wn + nt * 8 + (lane & 3) * 2;
            float2 v0 = make_float2(acc[mt][nt][0] + bias[ccol], acc[mt][nt][1] + bias[ccol + 1]);
            float2 v1 = make_float2(acc[mt][nt][2] + bias[ccol], acc[mt][nt][3] + bias[ccol + 1]);
            size_t i0 = (size_t)r0 * ldo + ccol;
            size_t i1 = (size_t)(r0 + 8) * ldo + ccol;
            if (resid) {
                v0.x += resid[i0]; v0.y += resid[i0 + 1];
                v1.x += resid[i1]; v1.y += resid[i1 + 1];
            }
            *reinterpret_cast<float2*>(&out[i0]) = v0;
            *reinterpret_cast<float2*>(&out[i1]) = v1;
        }
    }
}

// ---------- rank-1 softmax attention ----------
__global__ void __launch_bounds__(512)
attn_kernel(const float* __restrict__ theta, const float* __restrict__ phi,
            const float* __restrict__ g, float* __restrict__ y) {
    __shared__ float sth[4][DDIM], sg[4][DDIM], sred[4][8];
    const int tid = threadIdx.x, gr = tid >> 7, t = tid & 127;
    const int row = blockIdx.x * 4 + gr;

    float th = theta[(size_t)row * DDIM + t];
    sth[gr][t] = th;
    sg[gr][t] = g[(size_t)row * DDIM + t];

    float mx = th, mn = th;
#pragma unroll
    for (int off = 16; off >= 1; off >>= 1) {
        mx = fmaxf(mx, __shfl_xor_sync(0xffffffffu, mx, off));
        mn = fminf(mn, __shfl_xor_sync(0xffffffffu, mn, off));
    }
    if ((t & 31) == 0) {
        sred[gr][t >> 5] = mx;
        sred[gr][4 + (t >> 5)] = mn;
    }
    __syncthreads();
    float tmax = fmaxf(fmaxf(sred[gr][0], sred[gr][1]), fmaxf(sred[gr][2], sred[gr][3]));
    float tmin = fminf(fminf(sred[gr][4], sred[gr][5]), fminf(sred[gr][6], sred[gr][7]));

    float sc = phi[(size_t)row * DDIM + t] * 1.4426950408889634f;
    float m2 = sc * (sc >= 0.f ? tmax : tmin);

    float num = 0.f, den = 0.f;
#pragma unroll 8
    for (int j = 0; j < DDIM; j += 4) {
        float4 tv = *reinterpret_cast<const float4*>(&sth[gr][j]);
        float4 gv = *reinterpret_cast<const float4*>(&sg[gr][j]);
        float e0 = ex2f(fmaf(sc, tv.x, -m2));
        float e1 = ex2f(fmaf(sc, tv.y, -m2));
        float e2 = ex2f(fmaf(sc, tv.z, -m2));
        float e3 = ex2f(fmaf(sc, tv.w, -m2));
        num = fmaf(e0, gv.x, num); den += e0;
        num = fmaf(e1, gv.y, num); den += e1;
        num = fmaf(e2, gv.z, num); den += e2;
        num = fmaf(e3, gv.w, num); den += e3;
    }
    y[(size_t)row * DDIM + t] = num / den;
}

extern "C" void kernel_launch(void* const* d_in, const int* in_sizes, int n_in,
                              void* d_out, int out_size) {
    const float* x0   = (const float*)d_in[0];
    const float* x1   = (const float*)d_in[1];
    const float* g_w  = (const float*)d_in[2];
    const float* g_b  = (const float*)d_in[3];
    const float* th_w = (const float*)d_in[4];
    const float* th_b = (const float*)d_in[5];
    const float* ph_w = (const float*)d_in[6];
    const float* ph_b = (const float*)d_in[7];
    const float* W_w  = (const float*)d_in[8];
    const float* W_b  = (const float*)d_in[9];
    float* out = (float*)d_out;

    void *p_th, *p_ph, *p_g, *p_y;
    void *p_gwh, *p_gwl, *p_thwh, *p_thwl, *p_phwh, *p_phwl, *p_Wwh, *p_Wwl;
    cudaGetSymbolAddress(&p_th, s_theta);
    cudaGetSymbolAddress(&p_ph, s_phi);
    cudaGetSymbolAddress(&p_g, s_g);
    cudaGetSymbolAddress(&p_y, s_y);
    cudaGetSymbolAddress(&p_gwh, s_gwh);
    cudaGetSymbolAddress(&p_gwl, s_gwl);
    cudaGetSymbolAddress(&p_thwh, s_thwh);
    cudaGetSymbolAddress(&p_thwl, s_thwl);
    cudaGetSymbolAddress(&p_phwh, s_phwh);
    cudaGetSymbolAddress(&p_phwl, s_phwl);
    cudaGetSymbolAddress(&p_Wwh, s_Wwh);
    cudaGetSymbolAddress(&p_Wwl, s_Wwl);

    cudaFuncSetAttribute(gemm_split_kernel,
                         cudaFuncAttributeMaxDynamicSharedMemorySize, GEMM_SMEM);

    const int wn4 = DDIM * CDIM / 4;
    split_kernel<<<64, 256>>>(g_w,  (__nv_bfloat16*)p_gwh,  (__nv_bfloat16*)p_gwl,  wn4);
    split_kernel<<<64, 256>>>(th_w, (__nv_bfloat16*)p_thwh, (__nv_bfloat16*)p_thwl, wn4);
    split_kernel<<<64, 256>>>(ph_w, (__nv_bfloat16*)p_phwh, (__nv_bfloat16*)p_phwl, wn4);
    split_kernel<<<64, 256>>>(W_w,  (__nv_bfloat16*)p_Wwh,  (__nv_bfloat16*)p_Wwl,  wn4);

    gemm_split_kernel<<<dim3(BDIM / 128, 1), 256, GEMM_SMEM>>>(
        x0, (__nv_bfloat16*)p_gwh, (__nv_bfloat16*)p_gwl, g_b, nullptr,
        (float*)p_g, CDIM, DDIM);
    gemm_split_kernel<<<dim3(BDIM / 128, 1), 256, GEMM_SMEM>>>(
        x1, (__nv_bfloat16*)p_thwh, (__nv_bfloat16*)p_thwl, th_b, nullptr,
        (float*)p_th, CDIM, DDIM);
    gemm_split_kernel<<<dim3(BDIM / 128, 1), 256, GEMM_SMEM>>>(
        x1, (__nv_bfloat16*)p_phwh, (__nv_bfloat16*)p_phwl, ph_b, nullptr,
        (float*)p_ph, CDIM, DDIM);

    attn_kernel<<<BDIM / 4, 512>>>((const float*)p_th, (const float*)p_ph,
                                   (const float*)p_g, (float*)p_y);

    gemm_split_kernel<<<dim3(BDIM / 128, 8), 256, GEMM_SMEM>>>(
        (const float*)p_y, (__nv_bfloat16*)p_Wwh, (__nv_bfloat16*)p_Wwl, W_b, x0,
        out, DDIM, CDIM);
}